// round 15
// baseline (speedup 1.0000x reference)
#include <cuda_runtime.h>
#include <cuda_fp16.h>
#include <stdint.h>

#define TT    512
#define TOPK  2
#define NE    8
#define NH    2816
#define ND    1024
#define NPAIR 1024

// Scratch
__device__ int d_cnt[NE];
__device__ int d_slot[NE][NPAIR];
__device__ __align__(16) __half d_Gh[(size_t)NPAIR * NH];
__device__ __align__(16) __half d_xh[TT * ND];
__device__ __align__(16) __half d_w1h[(size_t)NE * NH * ND];
__device__ __align__(16) __half d_w3h[(size_t)NE * NH * ND];
__device__ __align__(16) __half d_w2t[(size_t)NE * ND * NH];   // transposed [e][d][h]

// ---------------------------------------------------------------------------
__device__ __forceinline__ uint32_t smem_u32(const void* p) {
    uint32_t a;
    asm("{ .reg .u64 t; cvta.to.shared.u64 t, %1; cvt.u32.u64 %0, t; }" : "=r"(a) : "l"(p));
    return a;
}
__device__ __forceinline__ void ldsm4(uint32_t* r, uint32_t addr) {
    asm volatile("ldmatrix.sync.aligned.m8n8.x4.shared.b16 {%0,%1,%2,%3}, [%4];"
        : "=r"(r[0]), "=r"(r[1]), "=r"(r[2]), "=r"(r[3]) : "r"(addr));
}
__device__ __forceinline__ void mma16816h(float* c, const uint32_t* a, const uint32_t* b) {
    asm volatile("mma.sync.aligned.m16n8k16.row.col.f32.f16.f16.f32 "
        "{%0,%1,%2,%3},{%4,%5,%6,%7},{%8,%9},{%0,%1,%2,%3};"
        : "+f"(c[0]), "+f"(c[1]), "+f"(c[2]), "+f"(c[3])
        : "r"(a[0]), "r"(a[1]), "r"(a[2]), "r"(a[3]), "r"(b[0]), "r"(b[1]));
}
__device__ __forceinline__ void cp16(uint32_t dst, const void* src) {
    asm volatile("cp.async.cg.shared.global [%0], [%1], 16;" :: "r"(dst), "l"(src) : "memory");
}
#define CP_COMMIT() asm volatile("cp.async.commit_group;" ::: "memory")
#define CP_WAIT1()  asm volatile("cp.async.wait_group 1;" ::: "memory")

__device__ __forceinline__ uint32_t pack2h(__half e0, __half e1) {
    return (uint32_t)__half_as_ushort(e0) | ((uint32_t)__half_as_ushort(e1) << 16);
}

// ---------------------------------------------------------------------------
__global__ void route_kernel(const int* __restrict__ eidx) {
    __shared__ int s_cnt[NE];
    int tid = threadIdx.x;
    if (tid < NE) s_cnt[tid] = 0;
    __syncthreads();
    int e = eidx[tid];
    int slot = atomicAdd(&s_cnt[e], 1);
    d_slot[e][slot] = tid;
    __syncthreads();
    if (tid < NE) d_cnt[tid] = s_cnt[tid];
}

__global__ void prep_x(const float* __restrict__ x) {
    size_t i = ((size_t)blockIdx.x * blockDim.x + threadIdx.x) * 4;
    float4 v = *(const float4*)(x + i);
    *(uint2*)(d_xh + i) = make_uint2(pack2h(__float2half_rn(v.x), __float2half_rn(v.y)),
                                     pack2h(__float2half_rn(v.z), __float2half_rn(v.w)));
}

#define W16_BLOCKS 45056
__global__ __launch_bounds__(256) void prep_w(
    const float* __restrict__ w1, const float* __restrict__ w3,
    const float* __restrict__ w2)
{
    __shared__ float sT[64][65];
    int bid = blockIdx.x;
    int tid = threadIdx.x;
    if (bid < W16_BLOCKS) {
        size_t nf4 = (size_t)NE * NH * ND / 4;
        size_t i = (size_t)bid * 256 + tid;
        const float* src = w1; __half* dst = d_w1h;
        if (i >= nf4) { src = w3; dst = d_w3h; i -= nf4; }
        float4 v = ((const float4*)src)[i];
        *(uint2*)(dst + i * 4) =
            make_uint2(pack2h(__float2half_rn(v.x), __float2half_rn(v.y)),
                       pack2h(__float2half_rn(v.z), __float2half_rn(v.w)));
        return;
    }
    int b  = bid - W16_BLOCKS;
    int xd = b & 15;
    int yh = (b >> 4) % 44;
    int e  = b / (16 * 44);
    {
        int row = tid >> 2;
        int seg = (tid & 3) * 16;
        const float* src = w2 + ((size_t)e * NH + yh * 64 + row) * ND + xd * 64 + seg;
        float4 a0 = ((const float4*)src)[0];
        float4 a1 = ((const float4*)src)[1];
        float4 a2 = ((const float4*)src)[2];
        float4 a3 = ((const float4*)src)[3];
        float t[16] = { a0.x,a0.y,a0.z,a0.w, a1.x,a1.y,a1.z,a1.w,
                        a2.x,a2.y,a2.z,a2.w, a3.x,a3.y,a3.z,a3.w };
        #pragma unroll
        for (int i = 0; i < 16; i++) sT[seg + i][row] = t[i];
    }
    __syncthreads();
    {
        int drow = tid >> 2;
        int hseg = (tid & 3) * 16;
        uint32_t o[8];
        #pragma unroll
        for (int i = 0; i < 8; i++)
            o[i] = pack2h(__float2half_rn(sT[drow][hseg + 2 * i]),
                          __float2half_rn(sT[drow][hseg + 2 * i + 1]));
        __half* dst = d_w2t + ((size_t)e * ND + xd * 64 + drow) * NH + yh * 64 + hseg;
        ((uint4*)dst)[0] = make_uint4(o[0], o[1], o[2], o[3]);
        ((uint4*)dst)[1] = make_uint4(o[4], o[5], o[6], o[7]);
    }
}

// ---------------------------------------------------------------------------
// GEMM1 fused: C1,C3[128 pairs x 64 h]; Gh = silu(C1)*C3 fp16.
// K=1024 in 8 chunks of 128 (two 64-k sub-tiles per chunk).
// 3-stage pipeline, single barrier per chunk, wait_group 1.
// Stage 64KB: A0 16K@0, A1 16K@16384, B1_0 8K@32768, B1_1 8K@40960,
//             B3_0 8K@49152, B3_1 8K@57344.
// ---------------------------------------------------------------------------
#define G1_STAGE 65536
#define G1_SMEM  (1024 + 3 * G1_STAGE)   // 197632

__global__ __launch_bounds__(512) void gemm1_mma(int dummy)
{
    int e = blockIdx.z;
    int cnt = d_cnt[e];
    int trow0 = blockIdx.y * 128;
    if (trow0 >= cnt) return;
    int col0 = blockIdx.x * 64;

    extern __shared__ char smem[];
    int* s_p   = (int*)smem;
    int* s_tok = (int*)(smem + 512);
    uint32_t sb = smem_u32(smem);

    int tid = threadIdx.x, lane = tid & 31, wid = tid >> 5;
    if (tid < 128) {
        int r = trow0 + tid;
        int p = (r < cnt) ? d_slot[e][r] : d_slot[e][0];
        s_p[tid] = p; s_tok[tid] = p >> 1;
    }
    __syncthreads();

    int arow = tid >> 2, aq = tid & 3;
    uint32_t aswz = (uint32_t)((arow & 7) << 4);
    const __half* xr = d_xh + (size_t)s_tok[arow] * ND + aq * 16;
    uint32_t off0 = (uint32_t)arow * 128 + (((uint32_t)(aq * 32)) ^ aswz);
    uint32_t off1 = (uint32_t)arow * 128 + (((uint32_t)(aq * 32 + 16)) ^ aswz);

    int brow = tid >> 3, bq = tid & 7;
    const __half* w1r = d_w1h + ((size_t)e * NH + col0 + brow) * ND + bq * 8;
    const __half* w3r = d_w3h + ((size_t)e * NH + col0 + brow) * ND + bq * 8;
    uint32_t boff = (uint32_t)brow * 128 +
        (((uint32_t)(bq * 16)) ^ (uint32_t)((brow & 7) << 4));

    float acc1[2][2][4], acc3[2][2][4];
    #pragma unroll
    for (int a = 0; a < 2; a++)
        #pragma unroll
        for (int b = 0; b < 2; b++)
            #pragma unroll
            for (int c = 0; c < 4; c++) { acc1[a][b][c] = 0.0f; acc3[a][b][c] = 0.0f; }

    int wm = wid & 3, wn = wid >> 2;   // 4 x 32 pairs, 4 x 16 h

    // chunk = 128 k; two 64-k halves
    #define G1_ISSUE(KC, ST) do { \
        uint32_t base = sb + 1024 + (ST) * G1_STAGE; \
        _Pragma("unroll") \
        for (int hf = 0; hf < 2; hf++) { \
            const char* sa = (const char*)(xr + (KC) * 128 + hf * 64); \
            cp16(base + hf * 16384 + off0, sa); \
            cp16(base + hf * 16384 + off1, sa + 16); \
            cp16(base + 32768 + hf * 8192 + boff, (const char*)(w1r + (KC) * 128 + hf * 64)); \
            cp16(base + 49152 + hf * 8192 + boff, (const char*)(w3r + (KC) * 128 + hf * 64)); \
        } \
    } while (0)

    G1_ISSUE(0, 0); CP_COMMIT();
    G1_ISSUE(1, 1); CP_COMMIT();

    #pragma unroll 1
    for (int kc = 0; kc < 8; kc++) {
        CP_WAIT1();
        __syncthreads();
        int st = kc % 3;
        int stN = (kc + 2) % 3;
        if (kc + 2 < 8) G1_ISSUE(kc + 2, stN);
        CP_COMMIT();

        uint32_t base = sb + 1024 + st * G1_STAGE;
        #pragma unroll
        for (int hf = 0; hf < 2; hf++) {
            uint32_t uA  = base + hf * 16384;
            uint32_t uB1 = base + 32768 + hf * 8192;
            uint32_t uB3 = base + 49152 + hf * 8192;
            #pragma unroll
            for (int ks = 0; ks < 4; ks++) {
                uint32_t Ah[2][4], B1h[4], B3h[4];
                int kb = ks * 32;
                #pragma unroll
                for (int mi = 0; mi < 2; mi++) {
                    int row = wm * 32 + mi * 16 + (lane & 15);
                    uint32_t bb = (uint32_t)(kb + ((lane >> 4) << 4));
                    uint32_t off = (uint32_t)row * 128 + (bb ^ (uint32_t)((row & 7) << 4));
                    ldsm4(Ah[mi], uA + off);
                }
                {
                    int row = wn * 16 + (lane & 7) + (((lane >> 4) & 1) << 3);
                    uint32_t bb = (uint32_t)(kb + (((lane >> 3) & 1) << 4));
                    uint32_t off = (uint32_t)row * 128 + (bb ^ (uint32_t)((row & 7) << 4));
                    ldsm4(B1h, uB1 + off);
                    ldsm4(B3h, uB3 + off);
                }
                #pragma unroll
                for (int mi = 0; mi < 2; mi++) {
                    mma16816h(acc1[mi][0], Ah[mi], &B1h[0]);
                    mma16816h(acc1[mi][1], Ah[mi], &B1h[2]);
                    mma16816h(acc3[mi][0], Ah[mi], &B3h[0]);
                    mma16816h(acc3[mi][1], Ah[mi], &B3h[2]);
                }
            }
        }
    }
    #undef G1_ISSUE

    // Epilogue: Gh = silu(c1) * c3
    int cntLoc = cnt - trow0; if (cntLoc > 128) cntLoc = 128;
    #pragma unroll
    for (int mi = 0; mi < 2; mi++) {
        int r0 = wm * 32 + mi * 16 + (lane >> 2);
        int r1 = r0 + 8;
        #pragma unroll
        for (int ni = 0; ni < 2; ni++) {
            int col = col0 + wn * 16 + ni * 8 + (lane & 3) * 2;
            if (r0 < cntLoc) {
                float a = acc1[mi][ni][0], b = acc1[mi][ni][1];
                float g0 = __fdividef(a, 1.0f + __expf(-a)) * acc3[mi][ni][0];
                float g1 = __fdividef(b, 1.0f + __expf(-b)) * acc3[mi][ni][1];
                *(uint32_t*)&d_Gh[(size_t)s_p[r0] * NH + col] =
                    pack2h(__float2half_rn(g0), __float2half_rn(g1));
            }
            if (r1 < cntLoc) {
                float a = acc1[mi][ni][2], b = acc1[mi][ni][3];
                float g0 = __fdividef(a, 1.0f + __expf(-a)) * acc3[mi][ni][2];
                float g1 = __fdividef(b, 1.0f + __expf(-b)) * acc3[mi][ni][3];
                *(uint32_t*)&d_Gh[(size_t)s_p[r1] * NH + col] =
                    pack2h(__float2half_rn(g0), __float2half_rn(g1));
            }
        }
    }
}

// ---------------------------------------------------------------------------
// GEMM2: C[64 pairs x 64 d] = G . w2t, K=2816 in 22 chunks of 128.
// 3-stage pipeline, single barrier, wait_group 1, 2 CTAs/SM.
// Stage 32KB: A0 8K@0, A1 8K@8192, B0 8K@16384, B1 8K@24576.
// ---------------------------------------------------------------------------
#define G2_STAGE 32768
#define G2_SMEM  (1024 + 3 * G2_STAGE)   // 99328

__global__ __launch_bounds__(512, 2) void gemm2_mma(float* __restrict__ out)
{
    int e = blockIdx.z;
    int cnt = d_cnt[e];
    int trow0 = blockIdx.y * 64;
    if (trow0 >= cnt) return;
    int col0 = blockIdx.x * 64;

    extern __shared__ char smem[];
    int* s_p = (int*)smem;
    uint32_t sb = smem_u32(smem);

    int tid = threadIdx.x, lane = tid & 31, wid = tid >> 5;
    if (tid < 64) {
        int r = trow0 + tid;
        s_p[tid] = (r < cnt) ? d_slot[e][r] : d_slot[e][0];
    }
    __syncthreads();

    int lrow = tid >> 3, lq = tid & 7;
    uint32_t loff = (uint32_t)lrow * 128 +
        (((uint32_t)(lq * 16)) ^ (uint32_t)((lrow & 7) << 4));
    const __half* gr = d_Gh + (size_t)s_p[lrow] * NH + lq * 8;
    const __half* br = d_w2t + ((size_t)e * ND + col0 + lrow) * NH + lq * 8;

    float acc[2][4];
    #pragma unroll
    for (int b = 0; b < 2; b++)
        #pragma unroll
        for (int c = 0; c < 4; c++) acc[b][c] = 0.0f;

    int wm = wid & 3, wn = wid >> 2;

    #define G2_ISSUE(KC, ST) do { \
        uint32_t base = sb + 1024 + (ST) * G2_STAGE; \
        _Pragma("unroll") \
        for (int hf = 0; hf < 2; hf++) { \
            cp16(base + hf * 8192 + loff, (const char*)(gr + (KC) * 128 + hf * 64)); \
            cp16(base + 16384 + hf * 8192 + loff, (const char*)(br + (KC) * 128 + hf * 64)); \
        } \
    } while (0)

    G2_ISSUE(0, 0); CP_COMMIT();
    G2_ISSUE(1, 1); CP_COMMIT();

    #pragma unroll 1
    for (int kc = 0; kc < 22; kc++) {
        CP_WAIT1();
        __syncthreads();
        int st = kc % 3;
        int stN = (kc + 2) % 3;
        if (kc + 2 < 22) G2_ISSUE(kc + 2, stN);
        CP_COMMIT();

        uint32_t base = sb + 1024 + st * G2_STAGE;
        #pragma unroll
        for (int hf = 0; hf < 2; hf++) {
            uint32_t uAH = base + hf * 8192;
            uint32_t uBH = base + 16384 + hf * 8192;
            #pragma unroll
            for (int ks = 0; ks < 4; ks++) {
                uint32_t Ah[4], Bh[4];
                int kb = ks * 32;
                {
                    int row = wm * 16 + (lane & 15);
                    uint32_t bb = (uint32_t)(kb + ((lane >> 4) << 4));
                    uint32_t off = (uint32_t)row * 128 + (bb ^ (uint32_t)((row & 7) << 4));
                    ldsm4(Ah, uAH + off);
                }
                {
                    int row = wn * 16 + (lane & 7) + (((lane >> 4) & 1) << 3);
                    uint32_t bb = (uint32_t)(kb + (((lane >> 3) & 1) << 4));
                    uint32_t off = (uint32_t)row * 128 + (bb ^ (uint32_t)((row & 7) << 4));
                    ldsm4(Bh, uBH + off);
                }
                mma16816h(acc[0], Ah, &Bh[0]);
                mma16816h(acc[1], Ah, &Bh[2]);
            }
        }
    }
    #undef G2_ISSUE

    int cntLoc = cnt - trow0; if (cntLoc > 64) cntLoc = 64;
    {
        int r0 = wm * 16 + (lane >> 2);
        int r1 = r0 + 8;
        #pragma unroll
        for (int ni = 0; ni < 2; ni++) {
            int col = col0 + wn * 16 + ni * 8 + (lane & 3) * 2;
            if (r0 < cntLoc)
                *(float2*)&out[(size_t)s_p[r0] * ND + col] =
                    make_float2(acc[ni][0], acc[ni][1]);
            if (r1 < cntLoc)
                *(float2*)&out[(size_t)s_p[r1] * ND + col] =
                    make_float2(acc[ni][2], acc[ni][3]);
        }
    }
}

// ---------------------------------------------------------------------------
extern "C" void kernel_launch(void* const* d_in, const int* in_sizes, int n_in,
                              void* d_out, int out_size) {
    const float* x    = (const float*)d_in[0];
    const int*   eidx = (const int*)d_in[1];   // int32 (JAX default int)
    const float* w1   = (const float*)d_in[2];
    const float* w2   = (const float*)d_in[3];
    const float* w3   = (const float*)d_in[4];
    float*       out  = (float*)d_out;

    static bool attr_done = false;
    if (!attr_done) {
        cudaFuncSetAttribute(gemm1_mma, cudaFuncAttributeMaxDynamicSharedMemorySize, G1_SMEM);
        cudaFuncSetAttribute(gemm2_mma, cudaFuncAttributeMaxDynamicSharedMemorySize, G2_SMEM);
        attr_done = true;
    }

    route_kernel<<<1, NPAIR>>>(eidx);
    prep_x<<<(TT * ND / 4) / 256, 256>>>(x);
    prep_w<<<W16_BLOCKS + 16 * 44 * NE, 256>>>(w1, w3, w2);

    dim3 g1(NH / 64, NPAIR / 128, NE);   // 44 x 8 x 8
    gemm1_mma<<<g1, 512, G1_SMEM>>>(0);

    dim3 g2(ND / 64, NPAIR / 64, NE);    // 16 x 16 x 8
    gemm2_mma<<<g2, 512, G2_SMEM>>>(out);
}